// round 10
// baseline (speedup 1.0000x reference)
#include <cuda_runtime.h>
#include <cuda_fp16.h>
#include <cstdint>

#define NB 32
#define NL 2048
#define ND 1024
#define NROWS (NB * NL)   // 65536

// scores GEMM tiling
#define BM 128
#define BN 128
#define BK 64
#define NTHREADS 256
#define NKIT (ND / BK)            // 16
#define NSTAGE 3
#define A_BYTES (BM * 128)        // 16 KB
#define B_BYTES (BN * 128)        // 16 KB
#define STAGE_BYTES (A_BYTES + B_BYTES)     // 32 KB
#define SMEM_BYTES (NSTAGE * STAGE_BYTES)   // 96 KB
#define NTILES (ND / BN)          // 8
#define MTILES (NROWS / BM)       // 512

#define LCH 16                    // weighted split-L chunks

// ---------------- scratch ----------------
__device__ __half g_ctx_h[(size_t)NROWS * ND];   // 128 MB
__device__ __half g_wb_h[ND * ND];               // 2 MB (Wa_s * 64, [n][d])
__device__ float g_ht[NB * ND];                  // 128 KB
__device__ float g_partial[NTILES * NROWS];      // 2 MB
__device__ float g_wpart[LCH][NB][ND];           // 2 MB

// ---------------- helpers ----------------
__device__ __forceinline__ uint32_t smem_u32(const void* p) {
    uint32_t a;
    asm("{ .reg .u64 t; cvta.to.shared.u64 t, %1; cvt.u32.u64 %0, t; }" : "=r"(a) : "l"(p));
    return a;
}
__device__ __forceinline__ void cpa16(uint32_t dst, const void* src) {
    asm volatile("cp.async.cg.shared.global [%0], [%1], 16;" :: "r"(dst), "l"(src));
}
__device__ __forceinline__ void cpa_commit() {
    asm volatile("cp.async.commit_group;" ::: "memory");
}
__device__ __forceinline__ void cpa_wait1() {
    asm volatile("cp.async.wait_group 1;" ::: "memory");
}
__device__ __forceinline__ void ldsm4(uint32_t* r, uint32_t addr) {
    asm volatile("ldmatrix.sync.aligned.m8n8.x4.shared.b16 {%0,%1,%2,%3}, [%4];"
                 : "=r"(r[0]), "=r"(r[1]), "=r"(r[2]), "=r"(r[3]) : "r"(addr));
}
__device__ __forceinline__ void mma16816(float* c, const uint32_t* a, uint32_t b0, uint32_t b1) {
    asm volatile("mma.sync.aligned.m16n8k16.row.col.f32.f16.f16.f32 "
                 "{%0,%1,%2,%3}, {%4,%5,%6,%7}, {%8,%9}, {%0,%1,%2,%3};"
                 : "+f"(c[0]), "+f"(c[1]), "+f"(c[2]), "+f"(c[3])
                 : "r"(a[0]), "r"(a[1]), "r"(a[2]), "r"(a[3]), "r"(b0), "r"(b1));
}
__device__ __forceinline__ uint32_t pack2(float a, float b) {
    __half2 h = __floats2half2_rn(a, b);
    return *reinterpret_cast<uint32_t*>(&h);
}

// ---------------- P0: convert context fp32 -> fp16 (high-MLP stream) ----------------
__global__ void ctx_convert(const float* __restrict__ ctx) {
    size_t base = (size_t)blockIdx.x * 256 + threadIdx.x;    // 8192 blocks
    const float4* src = (const float4*)ctx;
    uint2* dst = (uint2*)g_ctx_h;
    #pragma unroll
    for (int j = 0; j < 8; j++) {
        size_t g = base + (size_t)j * 2097152;               // 16M float4 groups
        float4 v = src[g];
        dst[g] = make_uint2(pack2(v.x, v.y), pack2(v.z, v.w));
    }
}

// ---------------- P1: convert Wa_s (scaled x64) -> fp16 ----------------
__global__ void wb_convert(const float* __restrict__ wa) {
    int n = blockIdx.x;
    const float* src = wa + (size_t)n * (2 * ND) + ND + threadIdx.x * 4;
    float4 v = *(const float4*)src;
    uint2* dst = (uint2*)(g_wb_h + (size_t)n * ND);
    dst[threadIdx.x] = make_uint2(pack2(v.x * 64.f, v.y * 64.f),
                                  pack2(v.z * 64.f, v.w * 64.f));
}

// ---------------- K0: ht_proj[b,k] = sum_d x[b,d]*Wa[k,d] (fp32) ----------------
__global__ void ht_kernel(const float* __restrict__ x, const float* __restrict__ wa) {
    int b = blockIdx.x, kb = blockIdx.y * 128;
    int warp = threadIdx.x >> 5, lane = threadIdx.x & 31;
    const float* xr = x + b * ND;
    for (int k = kb + warp; k < kb + 128; k += 8) {
        const float* wr = wa + (size_t)k * (2 * ND);
        float acc = 0.f;
        #pragma unroll 8
        for (int d = lane; d < ND; d += 32) acc += xr[d] * wr[d];
        #pragma unroll
        for (int o = 16; o; o >>= 1) acc += __shfl_xor_sync(0xFFFFFFFFu, acc, o);
        if (lane == 0) g_ht[b * ND + k] = acc;
    }
}

// ---------------- K1: scores partials via fp16 mma.sync GEMM ----------------
// grid 4096: mtile = bid>>3, ntile = bid&7. 256 thr, 2 CTAs/SM, warps 4x2,
// warp tile 32x64, BK=64, 3-stage cp.async.
__global__ void __launch_bounds__(NTHREADS, 2) scores_kernel(const float* __restrict__ va) {
    extern __shared__ char smem[];
    const uint32_t sbase = smem_u32(smem);

    const int tid = threadIdx.x;
    const int lane = tid & 31, wid = tid >> 5;
    const int wm = wid >> 1, wn = wid & 1;       // 4 x 2 warps
    const int g = lane >> 2, tig = lane & 3;
    const int lane7 = lane & 7;
    const int cSelA = lane >> 4;                 // 0/1
    const int cSelB = (lane >> 3) & 1;           // 0/1

    const int mtile = blockIdx.x >> 3, ntile = blockIdx.x & 7;
    const int rbase = mtile * BM;
    const int nbase = ntile * BN;
    const int b = rbase >> 11;

    const __half* gA = g_ctx_h + (size_t)rbase * ND;
    const __half* gB = g_wb_h + (size_t)nbase * ND;

    // cp.async per-thread assignments (256 thr: A 4 chunks, B 4 chunks)
    uint32_t aDst[4], bDst[4];
    uint32_t aSrcOff[4], bSrcOff[4];
    #pragma unroll
    for (int i = 0; i < 4; i++) {
        int id = tid * 4 + i, row = id >> 3, c = id & 7;
        uint32_t d = row * 128 + ((c ^ (row & 7)) << 4);
        aDst[i] = d;
        bDst[i] = A_BYTES + d;
        aSrcOff[i] = row * ND + c * 8;
        bSrcOff[i] = row * ND + c * 8;
    }

    // ldmatrix base offsets: warp rows wm*32 + mt*16, warp cols wn*64
    const int aRow = wm * 32 + ((lane >> 3) & 1) * 8 + lane7;
    const uint32_t aOff = (uint32_t)aRow * 128;
    uint32_t bOff[4];
    #pragma unroll
    for (int i = 0; i < 4; i++)
        bOff[i] = (uint32_t)(wn * 64 + i * 16 + ((lane >> 4) & 1) * 8 + lane7) * 128 + A_BYTES;

    float c[2][8][4];
    #pragma unroll
    for (int i = 0; i < 2; i++)
        #pragma unroll
        for (int j = 0; j < 8; j++)
            #pragma unroll
            for (int q = 0; q < 4; q++) c[i][j][q] = 0.f;

    // prologue: fill stages 0,1
    #pragma unroll
    for (int s = 0; s < 2; s++) {
        uint32_t st = sbase + s * STAGE_BYTES;
        const __half* a = gA + s * BK;
        const __half* bb = gB + s * BK;
        #pragma unroll
        for (int i = 0; i < 4; i++) cpa16(st + aDst[i], a + aSrcOff[i]);
        #pragma unroll
        for (int i = 0; i < 4; i++) cpa16(st + bDst[i], bb + bSrcOff[i]);
        cpa_commit();
    }

    int stage = 0;
    for (int ck = 0; ck < NKIT; ck++) {
        cpa_wait1();
        __syncthreads();

        // issue k-chunk ck+2 into stage (stage+2)%3
        if (ck + 2 < NKIT) {
            int s2 = stage + 2; if (s2 >= 3) s2 -= 3;
            uint32_t st = sbase + s2 * STAGE_BYTES;
            const __half* a = gA + (ck + 2) * BK;
            const __half* bb = gB + (ck + 2) * BK;
            #pragma unroll
            for (int i = 0; i < 4; i++) cpa16(st + aDst[i], a + aSrcOff[i]);
            #pragma unroll
            for (int i = 0; i < 4; i++) cpa16(st + bDst[i], bb + bSrcOff[i]);
        }
        cpa_commit();

        const uint32_t sA = sbase + stage * STAGE_BYTES;
        #pragma unroll
        for (int ks = 0; ks < 4; ks++) {
            uint32_t aSwz = (uint32_t)(((ks * 2 + cSelA) ^ lane7) << 4);
            uint32_t bSwz = (uint32_t)(((ks * 2 + cSelB) ^ lane7) << 4);
            uint32_t af[2][4], bf[4][4];
            #pragma unroll
            for (int mt = 0; mt < 2; mt++)
                ldsm4(af[mt], sA + aOff + mt * 2048 + aSwz);
            #pragma unroll
            for (int i = 0; i < 4; i++)
                ldsm4(bf[i], sA + bOff[i] + bSwz);
            #pragma unroll
            for (int mt = 0; mt < 2; mt++)
                #pragma unroll
                for (int n8 = 0; n8 < 8; n8++)
                    mma16816(c[mt][n8], af[mt], bf[n8 >> 1][(n8 & 1) * 2],
                             bf[n8 >> 1][(n8 & 1) * 2 + 1]);
        }
        stage++; if (stage >= 3) stage = 0;
    }
    __syncthreads();

    // ---- epilogue: p[row] = sum_col va[k]*tanh(ht[b,k] + C/64), cross-wn smem reduce ----
    float* sht  = (float*)smem;                 // [BN]
    float* sva  = sht + BN;                     // [BN]
    float* sred = sva + BN;                     // [2][BM]
    for (int i = tid; i < BN; i += NTHREADS) {
        sht[i] = g_ht[b * ND + nbase + i];
        sva[i] = va[nbase + i];
    }
    __syncthreads();

    const float inv = 1.0f / 64.0f;
    #pragma unroll
    for (int mt = 0; mt < 2; mt++) {
        float p0 = 0.f, p1 = 0.f;
        #pragma unroll
        for (int n8 = 0; n8 < 8; n8++) {
            #pragma unroll
            for (int j = 0; j < 2; j++) {
                int col = wn * 64 + n8 * 8 + tig * 2 + j;
                float hv = sht[col], vv = sva[col];
                p0 += vv * tanhf(hv + c[mt][n8][j] * inv);
                p1 += vv * tanhf(hv + c[mt][n8][2 + j] * inv);
            }
        }
        p0 += __shfl_xor_sync(0xFFFFFFFFu, p0, 1);
        p0 += __shfl_xor_sync(0xFFFFFFFFu, p0, 2);
        p1 += __shfl_xor_sync(0xFFFFFFFFu, p1, 1);
        p1 += __shfl_xor_sync(0xFFFFFFFFu, p1, 2);
        if (tig == 0) {
            int rl = wm * 32 + mt * 16 + g;
            sred[wn * BM + rl]     = p0;
            sred[wn * BM + rl + 8] = p1;
        }
    }
    __syncthreads();
    for (int i = tid; i < BM; i += NTHREADS) {
        float s = sred[i] + sred[BM + i];
        g_partial[(size_t)ntile * NROWS + rbase + i] = s;
    }
}

// ---------------- K2: sum partials + softmax -> out[NB*ND ..] ----------------
__global__ void softmax_kernel(float* __restrict__ out) {
    __shared__ float red[256];
    int b = blockIdx.x, tid = threadIdx.x;
    float v[8], mx = -1e30f;
    #pragma unroll
    for (int i = 0; i < 8; i++) {
        int idx = b * NL + i * 256 + tid;
        float s = 0.f;
        #pragma unroll
        for (int p = 0; p < NTILES; p++) s += g_partial[(size_t)p * NROWS + idx];
        v[i] = s;
        mx = fmaxf(mx, s);
    }
    red[tid] = mx; __syncthreads();
    for (int o = 128; o; o >>= 1) { if (tid < o) red[tid] = fmaxf(red[tid], red[tid + o]); __syncthreads(); }
    mx = red[0]; __syncthreads();
    float sum = 0.f;
    #pragma unroll
    for (int i = 0; i < 8; i++) { v[i] = expf(v[i] - mx); sum += v[i]; }
    red[tid] = sum; __syncthreads();
    for (int o = 128; o; o >>= 1) { if (tid < o) red[tid] += red[tid + o]; __syncthreads(); }
    float invs = 1.f / red[0];
    #pragma unroll
    for (int i = 0; i < 8; i++) out[NB * ND + b * NL + i * 256 + tid] = v[i] * invs;
}

// ---------------- K3a: weighted partials over L-chunks (fp16 ctx) ----------------
__global__ void weighted_part(const float* __restrict__ out_attn) {
    __shared__ float sa[NL / LCH];   // 128
    int lc = blockIdx.x, b = blockIdx.y, tid = threadIdx.x;
    for (int i = tid; i < NL / LCH; i += 128)
        sa[i] = out_attn[b * NL + lc * (NL / LCH) + i];
    __syncthreads();
    const uint4* cb = (const uint4*)(g_ctx_h + ((size_t)b * NL + (size_t)lc * (NL / LCH)) * ND) + tid;
    float acc[8] = {0,0,0,0,0,0,0,0};
    #pragma unroll 4
    for (int l = 0; l < NL / LCH; l++) {
        uint4 v = cb[l * (ND / 8)];
        float a = sa[l];
        const __half2* h = (const __half2*)&v;
        #pragma unroll
        for (int q = 0; q < 4; q++) {
            float2 f = __half22float2(h[q]);
            acc[q * 2]     += a * f.x;
            acc[q * 2 + 1] += a * f.y;
        }
    }
    #pragma unroll
    for (int q = 0; q < 8; q += 4)
        *(float4*)(&g_wpart[lc][b][tid * 8 + q]) =
            make_float4(acc[q], acc[q + 1], acc[q + 2], acc[q + 3]);
}

// ---------------- K3b: reduce partials -> out[0 .. NB*ND) ----------------
__global__ void weighted_reduce(float* __restrict__ out) {
    int b = blockIdx.x, tid = threadIdx.x;
    #pragma unroll
    for (int j = 0; j < 4; j++) {
        int d = j * 256 + tid;
        float s = 0.f;
        #pragma unroll
        for (int lc = 0; lc < LCH; lc++) s += g_wpart[lc][b][d];
        out[b * ND + d] = s;
    }
}

// ---------------- launch ----------------
extern "C" void kernel_launch(void* const* d_in, const int* in_sizes, int n_in,
                              void* d_out, int out_size) {
    const float* x   = (const float*)d_in[0];
    const float* ctx = (const float*)d_in[1];
    const float* wa  = (const float*)d_in[2];
    const float* va  = (const float*)d_in[3];
    float* out = (float*)d_out;

    cudaFuncSetAttribute(scores_kernel, cudaFuncAttributeMaxDynamicSharedMemorySize, SMEM_BYTES);

    ctx_convert<<<8192, 256>>>(ctx);
    wb_convert<<<ND, 256>>>(wa);
    dim3 gh(NB, 8);
    ht_kernel<<<gh, 256>>>(x, wa);
    scores_kernel<<<MTILES * NTILES, NTHREADS, SMEM_BYTES>>>(va);
    softmax_kernel<<<NB, 256>>>(out);
    dim3 g3(LCH, NB);
    weighted_part<<<g3, 128>>>(out + NB * ND);
    weighted_reduce<<<NB, 256>>>(out);
}

// round 11
// speedup vs baseline: 1.0101x; 1.0101x over previous
#include <cuda_runtime.h>
#include <cuda_fp16.h>
#include <cstdint>

#define NB 32
#define NL 2048
#define ND 1024
#define NROWS (NB * NL)   // 65536

// scores GEMM tiling
#define BM 128
#define BN 256
#define BK 64
#define NTHREADS 512
#define NKIT (ND / BK)            // 16
#define NSTAGE 4
#define A_BYTES (BM * 128)        // 16 KB
#define B_BYTES (BN * 128)        // 32 KB
#define STAGE_BYTES (A_BYTES + B_BYTES)     // 48 KB
#define SMEM_BYTES (NSTAGE * STAGE_BYTES)   // 192 KB
#define NTILES (ND / BN)          // 4
#define MTILES (NROWS / BM)       // 512

#define LCH 16                    // weighted split-L chunks

// ---------------- scratch ----------------
__device__ __half g_ctx_h[(size_t)NROWS * ND];   // 128 MB
__device__ __half g_wb_h[ND * ND];               // 2 MB (Wa_s * 64, [n][d])
__device__ float g_ht[NB * ND];                  // 128 KB
__device__ float g_partial[NTILES * NROWS];      // 1 MB
__device__ float g_wpart[LCH][NB][ND];           // 2 MB

// ---------------- helpers ----------------
__device__ __forceinline__ uint32_t smem_u32(const void* p) {
    uint32_t a;
    asm("{ .reg .u64 t; cvta.to.shared.u64 t, %1; cvt.u32.u64 %0, t; }" : "=r"(a) : "l"(p));
    return a;
}
__device__ __forceinline__ void cpa16(uint32_t dst, const void* src) {
    asm volatile("cp.async.cg.shared.global [%0], [%1], 16;" :: "r"(dst), "l"(src));
}
__device__ __forceinline__ void cpa_commit() {
    asm volatile("cp.async.commit_group;" ::: "memory");
}
__device__ __forceinline__ void cpa_wait2() {
    asm volatile("cp.async.wait_group 2;" ::: "memory");
}
__device__ __forceinline__ void ldsm4(uint32_t* r, uint32_t addr) {
    asm volatile("ldmatrix.sync.aligned.m8n8.x4.shared.b16 {%0,%1,%2,%3}, [%4];"
                 : "=r"(r[0]), "=r"(r[1]), "=r"(r[2]), "=r"(r[3]) : "r"(addr));
}
__device__ __forceinline__ void mma16816(float* c, const uint32_t* a, uint32_t b0, uint32_t b1) {
    asm volatile("mma.sync.aligned.m16n8k16.row.col.f32.f16.f16.f32 "
                 "{%0,%1,%2,%3}, {%4,%5,%6,%7}, {%8,%9}, {%0,%1,%2,%3};"
                 : "+f"(c[0]), "+f"(c[1]), "+f"(c[2]), "+f"(c[3])
                 : "r"(a[0]), "r"(a[1]), "r"(a[2]), "r"(a[3]), "r"(b0), "r"(b1));
}
__device__ __forceinline__ uint32_t pack2(float a, float b) {
    __half2 h = __floats2half2_rn(a, b);
    return *reinterpret_cast<uint32_t*>(&h);
}

// ---------------- P0: convert context fp32 -> fp16 (high-MLP stream) ----------------
__global__ void ctx_convert(const float* __restrict__ ctx) {
    size_t base = (size_t)blockIdx.x * 256 + threadIdx.x;    // 8192 blocks
    const float4* src = (const float4*)ctx;
    uint2* dst = (uint2*)g_ctx_h;
    #pragma unroll
    for (int j = 0; j < 8; j++) {
        size_t g = base + (size_t)j * 2097152;               // 16M float4 groups
        float4 v = src[g];
        dst[g] = make_uint2(pack2(v.x, v.y), pack2(v.z, v.w));
    }
}

// ---------------- P1: convert Wa_s (scaled x64) -> fp16 ----------------
__global__ void wb_convert(const float* __restrict__ wa) {
    int n = blockIdx.x;
    const float* src = wa + (size_t)n * (2 * ND) + ND + threadIdx.x * 4;
    float4 v = *(const float4*)src;
    uint2* dst = (uint2*)(g_wb_h + (size_t)n * ND);
    dst[threadIdx.x] = make_uint2(pack2(v.x * 64.f, v.y * 64.f),
                                  pack2(v.z * 64.f, v.w * 64.f));
}

// ---------------- K0: ht_proj[b,k] = sum_d x[b,d]*Wa[k,d] (fp32) ----------------
__global__ void ht_kernel(const float* __restrict__ x, const float* __restrict__ wa) {
    int b = blockIdx.x, kb = blockIdx.y * 128;
    int warp = threadIdx.x >> 5, lane = threadIdx.x & 31;
    const float* xr = x + b * ND;
    for (int k = kb + warp; k < kb + 128; k += 8) {
        const float* wr = wa + (size_t)k * (2 * ND);
        float acc = 0.f;
        #pragma unroll 8
        for (int d = lane; d < ND; d += 32) acc += xr[d] * wr[d];
        #pragma unroll
        for (int o = 16; o; o >>= 1) acc += __shfl_xor_sync(0xFFFFFFFFu, acc, o);
        if (lane == 0) g_ht[b * ND + k] = acc;
    }
}

// ---------------- K1: scores partials via fp16 mma.sync GEMM ----------------
// grid 2048: mtile = bid>>2, ntile = bid&3. 512 thr, warps 4x4, warp tile 32x64,
// BK=64, 4-stage cp.async, chunk body reordered: ldsm(ks0) -> cp.async -> mma.
__global__ void __launch_bounds__(NTHREADS, 1) scores_kernel(const float* __restrict__ va) {
    extern __shared__ char smem[];
    const uint32_t sbase = smem_u32(smem);

    const int tid = threadIdx.x;
    const int lane = tid & 31, wid = tid >> 5;
    const int wm = wid >> 2, wn = wid & 3;       // 4 x 4 warps
    const int g = lane >> 2, tig = lane & 3;
    const int lane7 = lane & 7;
    const int cSelA = lane >> 4;                 // 0/1
    const int cSelB = (lane >> 3) & 1;           // 0/1

    const int mtile = blockIdx.x >> 2, ntile = blockIdx.x & 3;
    const int rbase = mtile * BM;
    const int nbase = ntile * BN;
    const int b = rbase >> 11;

    const __half* gA = g_ctx_h + (size_t)rbase * ND;
    const __half* gB = g_wb_h + (size_t)nbase * ND;

    // cp.async per-thread assignments (512 thr: A 2 chunks, B 4 chunks)
    uint32_t aDst[2], bDst[4];
    uint32_t aSrcOff[2], bSrcOff[4];
    #pragma unroll
    for (int i = 0; i < 2; i++) {
        int id = tid * 2 + i, row = id >> 3, c = id & 7;
        aDst[i] = row * 128 + ((c ^ (row & 7)) << 4);
        aSrcOff[i] = row * ND + c * 8;
    }
    #pragma unroll
    for (int i = 0; i < 4; i++) {
        int id = tid * 4 + i, row = id >> 3, c = id & 7;
        bDst[i] = A_BYTES + row * 128 + ((c ^ (row & 7)) << 4);
        bSrcOff[i] = row * ND + c * 8;
    }

    // ldmatrix base offsets: warp rows wm*32 + mt*16, warp cols wn*64
    const int aRow = wm * 32 + ((lane >> 3) & 1) * 8 + lane7;
    const uint32_t aOff = (uint32_t)aRow * 128;
    uint32_t bOff[4];
    #pragma unroll
    for (int i = 0; i < 4; i++)
        bOff[i] = (uint32_t)(wn * 64 + i * 16 + ((lane >> 4) & 1) * 8 + lane7) * 128 + A_BYTES;

    float c[2][8][4];
    #pragma unroll
    for (int i = 0; i < 2; i++)
        #pragma unroll
        for (int j = 0; j < 8; j++)
            #pragma unroll
            for (int q = 0; q < 4; q++) c[i][j][q] = 0.f;

    // prologue: fill stages 0,1,2
    #pragma unroll
    for (int s = 0; s < 3; s++) {
        uint32_t st = sbase + s * STAGE_BYTES;
        const __half* a = gA + s * BK;
        const __half* bb = gB + s * BK;
        #pragma unroll
        for (int i = 0; i < 2; i++) cpa16(st + aDst[i], a + aSrcOff[i]);
        #pragma unroll
        for (int i = 0; i < 4; i++) cpa16(st + bDst[i], bb + bSrcOff[i]);
        cpa_commit();
    }

    int stage = 0;
    for (int ck = 0; ck < NKIT; ck++) {
        cpa_wait2();
        __syncthreads();

        const uint32_t sA = sbase + stage * STAGE_BYTES;

        // --- ks=0 fragments first (their latency is covered by the cp.async burst) ---
        uint32_t af[2][4], bf[4][4];
        {
            uint32_t aSwz = (uint32_t)((cSelA ^ lane7) << 4);
            uint32_t bSwz = (uint32_t)((cSelB ^ lane7) << 4);
            #pragma unroll
            for (int mt = 0; mt < 2; mt++)
                ldsm4(af[mt], sA + aOff + mt * 2048 + aSwz);
            #pragma unroll
            for (int i = 0; i < 4; i++)
                ldsm4(bf[i], sA + bOff[i] + bSwz);
        }

        // --- issue k-chunk ck+3 into stage (stage+3)%4 ---
        if (ck + 3 < NKIT) {
            int s3 = stage + 3; if (s3 >= NSTAGE) s3 -= NSTAGE;
            uint32_t st = sbase + s3 * STAGE_BYTES;
            const __half* a = gA + (ck + 3) * BK;
            const __half* bb = gB + (ck + 3) * BK;
            #pragma unroll
            for (int i = 0; i < 2; i++) cpa16(st + aDst[i], a + aSrcOff[i]);
            #pragma unroll
            for (int i = 0; i < 4; i++) cpa16(st + bDst[i], bb + bSrcOff[i]);
        }
        cpa_commit();

        // --- ks=0 MMAs, then ks=1..3 ---
        #pragma unroll
        for (int ks = 0; ks < 4; ks++) {
            if (ks > 0) {
                uint32_t aSwz = (uint32_t)(((ks * 2 + cSelA) ^ lane7) << 4);
                uint32_t bSwz = (uint32_t)(((ks * 2 + cSelB) ^ lane7) << 4);
                #pragma unroll
                for (int mt = 0; mt < 2; mt++)
                    ldsm4(af[mt], sA + aOff + mt * 2048 + aSwz);
                #pragma unroll
                for (int i = 0; i < 4; i++)
                    ldsm4(bf[i], sA + bOff[i] + bSwz);
            }
            #pragma unroll
            for (int mt = 0; mt < 2; mt++)
                #pragma unroll
                for (int n8 = 0; n8 < 8; n8++)
                    mma16816(c[mt][n8], af[mt], bf[n8 >> 1][(n8 & 1) * 2],
                             bf[n8 >> 1][(n8 & 1) * 2 + 1]);
        }
        stage++; if (stage >= NSTAGE) stage = 0;
    }
    __syncthreads();

    // ---- epilogue: p[row] = sum_col va[k]*tanh(ht[b,k] + C/64), cross-wn smem reduce ----
    float* sht  = (float*)smem;                 // [BN]
    float* sva  = sht + BN;                     // [BN]
    float* sred = sva + BN;                     // [4][BM]
    for (int i = tid; i < BN; i += NTHREADS) {
        sht[i] = g_ht[b * ND + nbase + i];
        sva[i] = va[nbase + i];
    }
    __syncthreads();

    const float inv = 1.0f / 64.0f;
    #pragma unroll
    for (int mt = 0; mt < 2; mt++) {
        float p0 = 0.f, p1 = 0.f;
        #pragma unroll
        for (int n8 = 0; n8 < 8; n8++) {
            #pragma unroll
            for (int j = 0; j < 2; j++) {
                int col = wn * 64 + n8 * 8 + tig * 2 + j;
                float hv = sht[col], vv = sva[col];
                p0 += vv * tanhf(hv + c[mt][n8][j] * inv);
                p1 += vv * tanhf(hv + c[mt][n8][2 + j] * inv);
            }
        }
        p0 += __shfl_xor_sync(0xFFFFFFFFu, p0, 1);
        p0 += __shfl_xor_sync(0xFFFFFFFFu, p0, 2);
        p1 += __shfl_xor_sync(0xFFFFFFFFu, p1, 1);
        p1 += __shfl_xor_sync(0xFFFFFFFFu, p1, 2);
        if (tig == 0) {
            int rl = wm * 32 + mt * 16 + g;
            sred[wn * BM + rl]     = p0;
            sred[wn * BM + rl + 8] = p1;
        }
    }
    __syncthreads();
    for (int i = tid; i < BM; i += NTHREADS) {
        float s = sred[i] + sred[BM + i] + sred[2 * BM + i] + sred[3 * BM + i];
        g_partial[(size_t)ntile * NROWS + rbase + i] = s;
    }
}

// ---------------- K2: sum partials + softmax -> out[NB*ND ..] ----------------
__global__ void softmax_kernel(float* __restrict__ out) {
    __shared__ float red[256];
    int b = blockIdx.x, tid = threadIdx.x;
    float v[8], mx = -1e30f;
    #pragma unroll
    for (int i = 0; i < 8; i++) {
        int idx = b * NL + i * 256 + tid;
        float s = 0.f;
        #pragma unroll
        for (int p = 0; p < NTILES; p++) s += g_partial[(size_t)p * NROWS + idx];
        v[i] = s;
        mx = fmaxf(mx, s);
    }
    red[tid] = mx; __syncthreads();
    for (int o = 128; o; o >>= 1) { if (tid < o) red[tid] = fmaxf(red[tid], red[tid + o]); __syncthreads(); }
    mx = red[0]; __syncthreads();
    float sum = 0.f;
    #pragma unroll
    for (int i = 0; i < 8; i++) { v[i] = expf(v[i] - mx); sum += v[i]; }
    red[tid] = sum; __syncthreads();
    for (int o = 128; o; o >>= 1) { if (tid < o) red[tid] += red[tid + o]; __syncthreads(); }
    float invs = 1.f / red[0];
    #pragma unroll
    for (int i = 0; i < 8; i++) out[NB * ND + b * NL + i * 256 + tid] = v[i] * invs;
}

// ---------------- K3a: weighted partials over L-chunks (fp16 ctx) ----------------
__global__ void weighted_part(const float* __restrict__ out_attn) {
    __shared__ float sa[NL / LCH];   // 128
    int lc = blockIdx.x, b = blockIdx.y, tid = threadIdx.x;
    for (int i = tid; i < NL / LCH; i += 128)
        sa[i] = out_attn[b * NL + lc * (NL / LCH) + i];
    __syncthreads();
    const uint4* cb = (const uint4*)(g_ctx_h + ((size_t)b * NL + (size_t)lc * (NL / LCH)) * ND) + tid;
    float acc[8] = {0,0,0,0,0,0,0,0};
    #pragma unroll 4
    for (int l = 0; l < NL / LCH; l++) {
        uint4 v = cb[l * (ND / 8)];
        float a = sa[l];
        const __half2* h = (const __half2*)&v;
        #pragma unroll
        for (int q = 0; q < 4; q++) {
            float2 f = __half22float2(h[q]);
            acc[q * 2]     += a * f.x;
            acc[q * 2 + 1] += a * f.y;
        }
    }
    #pragma unroll
    for (int q = 0; q < 8; q += 4)
        *(float4*)(&g_wpart[lc][b][tid * 8 + q]) =
            make_float4(acc[q], acc[q + 1], acc[q + 2], acc[q + 3]);
}

// ---------------- K3b: reduce partials -> out[0 .. NB*ND) ----------------
__global__ void weighted_reduce(float* __restrict__ out) {
    int b = blockIdx.x, tid = threadIdx.x;
    #pragma unroll
    for (int j = 0; j < 4; j++) {
        int d = j * 256 + tid;
        float s = 0.f;
        #pragma unroll
        for (int lc = 0; lc < LCH; lc++) s += g_wpart[lc][b][d];
        out[b * ND + d] = s;
    }
}

// ---------------- launch ----------------
extern "C" void kernel_launch(void* const* d_in, const int* in_sizes, int n_in,
                              void* d_out, int out_size) {
    const float* x   = (const float*)d_in[0];
    const float* ctx = (const float*)d_in[1];
    const float* wa  = (const float*)d_in[2];
    const float* va  = (const float*)d_in[3];
    float* out = (float*)d_out;

    cudaFuncSetAttribute(scores_kernel, cudaFuncAttributeMaxDynamicSharedMemorySize, SMEM_BYTES);

    ctx_convert<<<8192, 256>>>(ctx);
    wb_convert<<<ND, 256>>>(wa);
    dim3 gh(NB, 8);
    ht_kernel<<<gh, 256>>>(x, wa);
    scores_kernel<<<MTILES * NTILES, NTHREADS, SMEM_BYTES>>>(va);
    softmax_kernel<<<NB, 256>>>(out);
    dim3 g3(LCH, NB);
    weighted_part<<<g3, 128>>>(out + NB * ND);
    weighted_reduce<<<NB, 256>>>(out);
}

// round 13
// speedup vs baseline: 1.0613x; 1.0507x over previous
#include <cuda_runtime.h>
#include <cuda_fp16.h>
#include <cstdint>

#define NB 32
#define NL 2048
#define ND 1024
#define NROWS (NB * NL)   // 65536

// scores GEMM tiling
#define BM 128
#define BN 256
#define BK 64
#define NTHREADS 512
#define NKIT (ND / BK)            // 16
#define NSTAGE 4
#define A_BYTES (BM * 128)        // 16 KB
#define B_BYTES (BN * 128)        // 32 KB
#define STAGE_BYTES (A_BYTES + B_BYTES)     // 48 KB
#define SMEM_BYTES (NSTAGE * STAGE_BYTES)   // 192 KB
#define NTILES (ND / BN)          // 4
#define MTILES (NROWS / BM)       // 512

#define LCH 32                    // weighted split-L chunks (64 rows each)

// ---------------- scratch ----------------
__device__ __half g_ctx_h[(size_t)NROWS * ND];   // 128 MB
__device__ __half g_wb_h[ND * ND];               // 2 MB (Wa_s * 64, [n][d])
__device__ float g_ht[NB * ND];                  // 128 KB
__device__ float g_partial[NTILES * NROWS];      // 1 MB
__device__ float g_wpart[LCH][NB][ND];           // 4 MB

// ---------------- helpers ----------------
__device__ __forceinline__ uint32_t smem_u32(const void* p) {
    uint32_t a;
    asm("{ .reg .u64 t; cvta.to.shared.u64 t, %1; cvt.u32.u64 %0, t; }" : "=r"(a) : "l"(p));
    return a;
}
__device__ __forceinline__ void cpa16(uint32_t dst, const void* src) {
    asm volatile("cp.async.cg.shared.global [%0], [%1], 16;" :: "r"(dst), "l"(src));
}
__device__ __forceinline__ void cpa_commit() {
    asm volatile("cp.async.commit_group;" ::: "memory");
}
__device__ __forceinline__ void cpa_wait2() {
    asm volatile("cp.async.wait_group 2;" ::: "memory");
}
__device__ __forceinline__ void ldsm4(uint32_t* r, uint32_t addr) {
    asm volatile("ldmatrix.sync.aligned.m8n8.x4.shared.b16 {%0,%1,%2,%3}, [%4];"
                 : "=r"(r[0]), "=r"(r[1]), "=r"(r[2]), "=r"(r[3]) : "r"(addr));
}
__device__ __forceinline__ void mma16816(float* c, const uint32_t* a, uint32_t b0, uint32_t b1) {
    asm volatile("mma.sync.aligned.m16n8k16.row.col.f32.f16.f16.f32 "
                 "{%0,%1,%2,%3}, {%4,%5,%6,%7}, {%8,%9}, {%0,%1,%2,%3};"
                 : "+f"(c[0]), "+f"(c[1]), "+f"(c[2]), "+f"(c[3])
                 : "r"(a[0]), "r"(a[1]), "r"(a[2]), "r"(a[3]), "r"(b0), "r"(b1));
}
__device__ __forceinline__ uint32_t pack2(float a, float b) {
    __half2 h = __floats2half2_rn(a, b);
    return *reinterpret_cast<uint32_t*>(&h);
}

// ---------------- P0: convert context fp32 -> fp16 (high-MLP stream) ----------------
__global__ void ctx_convert(const float* __restrict__ ctx) {
    size_t base = (size_t)blockIdx.x * 256 + threadIdx.x;    // 8192 blocks
    const float4* src = (const float4*)ctx;
    uint2* dst = (uint2*)g_ctx_h;
    #pragma unroll
    for (int j = 0; j < 8; j++) {
        size_t g = base + (size_t)j * 2097152;               // 16M float4 groups
        float4 v = src[g];
        dst[g] = make_uint2(pack2(v.x, v.y), pack2(v.z, v.w));
    }
}

// ---------------- P1: convert Wa_s (scaled x64) -> fp16 ----------------
__global__ void wb_convert(const float* __restrict__ wa) {
    int n = blockIdx.x;
    const float* src = wa + (size_t)n * (2 * ND) + ND + threadIdx.x * 4;
    float4 v = *(const float4*)src;
    uint2* dst = (uint2*)(g_wb_h + (size_t)n * ND);
    dst[threadIdx.x] = make_uint2(pack2(v.x * 64.f, v.y * 64.f),
                                  pack2(v.z * 64.f, v.w * 64.f));
}

// ---------------- K0: ht_proj[b,k] = sum_d x[b,d]*Wa[k,d] (fp32) ----------------
__global__ void ht_kernel(const float* __restrict__ x, const float* __restrict__ wa) {
    int b = blockIdx.x, kb = blockIdx.y * 128;
    int warp = threadIdx.x >> 5, lane = threadIdx.x & 31;
    const float* xr = x + b * ND;
    for (int k = kb + warp; k < kb + 128; k += 8) {
        const float* wr = wa + (size_t)k * (2 * ND);
        float acc = 0.f;
        #pragma unroll 8
        for (int d = lane; d < ND; d += 32) acc += xr[d] * wr[d];
        #pragma unroll
        for (int o = 16; o; o >>= 1) acc += __shfl_xor_sync(0xFFFFFFFFu, acc, o);
        if (lane == 0) g_ht[b * ND + k] = acc;
    }
}

// ---------------- K1: scores partials via fp16 mma.sync GEMM (frozen) ----------------
__global__ void __launch_bounds__(NTHREADS, 1) scores_kernel(const float* __restrict__ va) {
    extern __shared__ char smem[];
    const uint32_t sbase = smem_u32(smem);

    const int tid = threadIdx.x;
    const int lane = tid & 31, wid = tid >> 5;
    const int wm = wid >> 2, wn = wid & 3;       // 4 x 4 warps
    const int g = lane >> 2, tig = lane & 3;
    const int lane7 = lane & 7;
    const int cSelA = lane >> 4;                 // 0/1
    const int cSelB = (lane >> 3) & 1;           // 0/1

    const int mtile = blockIdx.x >> 2, ntile = blockIdx.x & 3;
    const int rbase = mtile * BM;
    const int nbase = ntile * BN;
    const int b = rbase >> 11;

    const __half* gA = g_ctx_h + (size_t)rbase * ND;
    const __half* gB = g_wb_h + (size_t)nbase * ND;

    uint32_t aDst[2], bDst[4];
    uint32_t aSrcOff[2], bSrcOff[4];
    #pragma unroll
    for (int i = 0; i < 2; i++) {
        int id = tid * 2 + i, row = id >> 3, c = id & 7;
        aDst[i] = row * 128 + ((c ^ (row & 7)) << 4);
        aSrcOff[i] = row * ND + c * 8;
    }
    #pragma unroll
    for (int i = 0; i < 4; i++) {
        int id = tid * 4 + i, row = id >> 3, c = id & 7;
        bDst[i] = A_BYTES + row * 128 + ((c ^ (row & 7)) << 4);
        bSrcOff[i] = row * ND + c * 8;
    }

    const int aRow = wm * 32 + ((lane >> 3) & 1) * 8 + lane7;
    const uint32_t aOff = (uint32_t)aRow * 128;
    uint32_t bOff[4];
    #pragma unroll
    for (int i = 0; i < 4; i++)
        bOff[i] = (uint32_t)(wn * 64 + i * 16 + ((lane >> 4) & 1) * 8 + lane7) * 128 + A_BYTES;

    float c[2][8][4];
    #pragma unroll
    for (int i = 0; i < 2; i++)
        #pragma unroll
        for (int j = 0; j < 8; j++)
            #pragma unroll
            for (int q = 0; q < 4; q++) c[i][j][q] = 0.f;

    #pragma unroll
    for (int s = 0; s < 3; s++) {
        uint32_t st = sbase + s * STAGE_BYTES;
        const __half* a = gA + s * BK;
        const __half* bb = gB + s * BK;
        #pragma unroll
        for (int i = 0; i < 2; i++) cpa16(st + aDst[i], a + aSrcOff[i]);
        #pragma unroll
        for (int i = 0; i < 4; i++) cpa16(st + bDst[i], bb + bSrcOff[i]);
        cpa_commit();
    }

    int stage = 0;
    for (int ck = 0; ck < NKIT; ck++) {
        cpa_wait2();
        __syncthreads();

        const uint32_t sA = sbase + stage * STAGE_BYTES;

        uint32_t af[2][4], bf[4][4];
        {
            uint32_t aSwz = (uint32_t)((cSelA ^ lane7) << 4);
            uint32_t bSwz = (uint32_t)((cSelB ^ lane7) << 4);
            #pragma unroll
            for (int mt = 0; mt < 2; mt++)
                ldsm4(af[mt], sA + aOff + mt * 2048 + aSwz);
            #pragma unroll
            for (int i = 0; i < 4; i++)
                ldsm4(bf[i], sA + bOff[i] + bSwz);
        }

        if (ck + 3 < NKIT) {
            int s3 = stage + 3; if (s3 >= NSTAGE) s3 -= NSTAGE;
            uint32_t st = sbase + s3 * STAGE_BYTES;
            const __half* a = gA + (ck + 3) * BK;
            const __half* bb = gB + (ck + 3) * BK;
            #pragma unroll
            for (int i = 0; i < 2; i++) cpa16(st + aDst[i], a + aSrcOff[i]);
            #pragma unroll
            for (int i = 0; i < 4; i++) cpa16(st + bDst[i], bb + bSrcOff[i]);
        }
        cpa_commit();

        #pragma unroll
        for (int ks = 0; ks < 4; ks++) {
            if (ks > 0) {
                uint32_t aSwz = (uint32_t)(((ks * 2 + cSelA) ^ lane7) << 4);
                uint32_t bSwz = (uint32_t)(((ks * 2 + cSelB) ^ lane7) << 4);
                #pragma unroll
                for (int mt = 0; mt < 2; mt++)
                    ldsm4(af[mt], sA + aOff + mt * 2048 + aSwz);
                #pragma unroll
                for (int i = 0; i < 4; i++)
                    ldsm4(bf[i], sA + bOff[i] + bSwz);
            }
            #pragma unroll
            for (int mt = 0; mt < 2; mt++)
                #pragma unroll
                for (int n8 = 0; n8 < 8; n8++)
                    mma16816(c[mt][n8], af[mt], bf[n8 >> 1][(n8 & 1) * 2],
                             bf[n8 >> 1][(n8 & 1) * 2 + 1]);
        }
        stage++; if (stage >= NSTAGE) stage = 0;
    }
    __syncthreads();

    float* sht  = (float*)smem;                 // [BN]
    float* sva  = sht + BN;                     // [BN]
    float* sred = sva + BN;                     // [4][BM]
    for (int i = tid; i < BN; i += NTHREADS) {
        sht[i] = g_ht[b * ND + nbase + i];
        sva[i] = va[nbase + i];
    }
    __syncthreads();

    const float inv = 1.0f / 64.0f;
    #pragma unroll
    for (int mt = 0; mt < 2; mt++) {
        float p0 = 0.f, p1 = 0.f;
        #pragma unroll
        for (int n8 = 0; n8 < 8; n8++) {
            #pragma unroll
            for (int j = 0; j < 2; j++) {
                int col = wn * 64 + n8 * 8 + tig * 2 + j;
                float hv = sht[col], vv = sva[col];
                p0 += vv * tanhf(hv + c[mt][n8][j] * inv);
                p1 += vv * tanhf(hv + c[mt][n8][2 + j] * inv);
            }
        }
        p0 += __shfl_xor_sync(0xFFFFFFFFu, p0, 1);
        p0 += __shfl_xor_sync(0xFFFFFFFFu, p0, 2);
        p1 += __shfl_xor_sync(0xFFFFFFFFu, p1, 1);
        p1 += __shfl_xor_sync(0xFFFFFFFFu, p1, 2);
        if (tig == 0) {
            int rl = wm * 32 + mt * 16 + g;
            sred[wn * BM + rl]     = p0;
            sred[wn * BM + rl + 8] = p1;
        }
    }
    __syncthreads();
    for (int i = tid; i < BM; i += NTHREADS) {
        float s = sred[i] + sred[BM + i] + sred[2 * BM + i] + sred[3 * BM + i];
        g_partial[(size_t)ntile * NROWS + rbase + i] = s;
    }
}

// ---------------- K2: sum partials + softmax -> out[NB*ND ..] ----------------
__global__ void softmax_kernel(float* __restrict__ out) {
    __shared__ float red[256];
    int b = blockIdx.x, tid = threadIdx.x;
    float v[8], mx = -1e30f;
    #pragma unroll
    for (int i = 0; i < 8; i++) {
        int idx = b * NL + i * 256 + tid;
        float s = 0.f;
        #pragma unroll
        for (int p = 0; p < NTILES; p++) s += g_partial[(size_t)p * NROWS + idx];
        v[i] = s;
        mx = fmaxf(mx, s);
    }
    red[tid] = mx; __syncthreads();
    for (int o = 128; o; o >>= 1) { if (tid < o) red[tid] = fmaxf(red[tid], red[tid + o]); __syncthreads(); }
    mx = red[0]; __syncthreads();
    float sum = 0.f;
    #pragma unroll
    for (int i = 0; i < 8; i++) { v[i] = expf(v[i] - mx); sum += v[i]; }
    red[tid] = sum; __syncthreads();
    for (int o = 128; o; o >>= 1) { if (tid < o) red[tid] += red[tid + o]; __syncthreads(); }
    float invs = 1.f / red[0];
    #pragma unroll
    for (int i = 0; i < 8; i++) out[NB * ND + b * NL + i * 256 + tid] = v[i] * invs;
}

// ---------------- K3a: weighted partials over L-chunks (fp16 ctx) ----------------
// grid (LCH=32, NB), 128 thr: 64 L-rows per block, thread owns 8 d's, unroll 8.
__global__ void weighted_part(const float* __restrict__ out_attn) {
    __shared__ float sa[NL / LCH];   // 64
    int lc = blockIdx.x, b = blockIdx.y, tid = threadIdx.x;
    for (int i = tid; i < NL / LCH; i += 128)
        sa[i] = out_attn[b * NL + lc * (NL / LCH) + i];
    __syncthreads();
    const uint4* cb = (const uint4*)(g_ctx_h + ((size_t)b * NL + (size_t)lc * (NL / LCH)) * ND) + tid;
    float acc[8] = {0,0,0,0,0,0,0,0};
    #pragma unroll 8
    for (int l = 0; l < NL / LCH; l++) {
        uint4 v = cb[l * (ND / 8)];
        float a = sa[l];
        const __half2* h = (const __half2*)&v;
        #pragma unroll
        for (int q = 0; q < 4; q++) {
            float2 f = __half22float2(h[q]);
            acc[q * 2]     += a * f.x;
            acc[q * 2 + 1] += a * f.y;
        }
    }
    #pragma unroll
    for (int q = 0; q < 8; q += 4)
        *(float4*)(&g_wpart[lc][b][tid * 8 + q]) =
            make_float4(acc[q], acc[q + 1], acc[q + 2], acc[q + 3]);
}

// ---------------- K3b: reduce partials -> out[0 .. NB*ND) ----------------
__global__ void weighted_reduce(float* __restrict__ out) {
    int b = blockIdx.x, tid = threadIdx.x;
    #pragma unroll
    for (int j = 0; j < 4; j++) {
        int d = j * 256 + tid;
        float s = 0.f;
        #pragma unroll
        for (int lc = 0; lc < LCH; lc++) s += g_wpart[lc][b][d];
        out[b * ND + d] = s;
    }
}

// ---------------- launch ----------------
extern "C" void kernel_launch(void* const* d_in, const int* in_sizes, int n_in,
                              void* d_out, int out_size) {
    const float* x   = (const float*)d_in[0];
    const float* ctx = (const float*)d_in[1];
    const float* wa  = (const float*)d_in[2];
    const float* va  = (const float*)d_in[3];
    float* out = (float*)d_out;

    static cudaStream_t s1 = nullptr;
    static cudaEvent_t eFork = nullptr, eJoin = nullptr;
    if (s1 == nullptr) {
        cudaStreamCreateWithFlags(&s1, cudaStreamNonBlocking);
        cudaEventCreateWithFlags(&eFork, cudaEventDisableTiming);
        cudaEventCreateWithFlags(&eJoin, cudaEventDisableTiming);
        cudaFuncSetAttribute(scores_kernel, cudaFuncAttributeMaxDynamicSharedMemorySize, SMEM_BYTES);
    }

    // fork: wb_convert + ht_kernel run concurrently with ctx_convert
    cudaEventRecord(eFork, 0);
    cudaStreamWaitEvent(s1, eFork, 0);
    wb_convert<<<ND, 256, 0, s1>>>(wa);
    dim3 gh(NB, 8);
    ht_kernel<<<gh, 256, 0, s1>>>(x, wa);
    cudaEventRecord(eJoin, s1);

    ctx_convert<<<8192, 256>>>(ctx);
    cudaStreamWaitEvent(0, eJoin, 0);

    scores_kernel<<<MTILES * NTILES, NTHREADS, SMEM_BYTES>>>(va);
    softmax_kernel<<<NB, 256>>>(out);
    dim3 g3(LCH, NB);
    weighted_part<<<g3, 128>>>(out + NB * ND);
    weighted_reduce<<<NB, 256>>>(out);
}